// round 16
// baseline (speedup 1.0000x reference)
#include <cuda_runtime.h>
#include <cuda_fp16.h>

#define NMAX 100000
#define EMAX 1600000
#define HIDD 64
#define FIN  128

__device__ int     g_cnt[NMAX];
__device__ int     g_off[NMAX + 1];
__device__ int     g_cur[NMAX];
__device__ int     g_esrc[EMAX];
__device__ int     g_eidx[EMAX];
__device__ int     g_bsum[512];
__device__ float   g_dinv[NMAX];
__device__ __half2 g_hl2[NMAX * HIDD / 2];   // layer-1 linear (UNscaled); layer-2 pre-scaled
__device__ __half2 g_h2 [NMAX * HIDD / 2];   // fp16 aggregated features
__device__ __half2 g_ab2[NMAX * HIDD];       // fp16 [A|B] table
__device__ __half  g_w1h[FIN * HIDD];
__device__ __half  g_w2h[HIDD * HIDD];
__device__ __half  g_wabh[HIDD * 2 * HIDD];

static cudaStream_t g_s2;
static cudaEvent_t g_evFork, g_evJoin;
namespace { struct StreamInit {
    StreamInit() {
        cudaStreamCreateWithFlags(&g_s2, cudaStreamNonBlocking);
        cudaEventCreateWithFlags(&g_evFork, cudaEventDisableTiming);
        cudaEventCreateWithFlags(&g_evJoin, cudaEventDisableTiming);
    }
} g_streamInit; }

// ---------------- CSC build ----------------
__global__ void count_in(const int* __restrict__ col, int* __restrict__ cnt, int E) {
    int e = blockIdx.x * blockDim.x + threadIdx.x;
    if (e < E) atomicAdd(&cnt[col[e]], 1);
}
__global__ void scan1(const int* __restrict__ cnt, int* __restrict__ off,
                      int* __restrict__ bsum, float* __restrict__ dinv, int n) {
    __shared__ int s[256];
    int tid = threadIdx.x;
    int i = blockIdx.x * 256 + tid;
    int v = (i < n) ? cnt[i] : 0;
    if (i < n) dinv[i] = rsqrtf((float)v + 1.0f);
    s[tid] = v;
    __syncthreads();
#pragma unroll
    for (int d = 1; d < 256; d <<= 1) {
        int t = (tid >= d) ? s[tid - d] : 0;
        __syncthreads();
        s[tid] += t;
        __syncthreads();
    }
    if (i < n) off[i] = s[tid] - v;
    if (tid == 255) bsum[blockIdx.x] = s[255];
}
__global__ void scan2(int* __restrict__ bsum, int nb) {
    __shared__ int s[512];
    int tid = threadIdx.x;
    int v = (tid < nb) ? bsum[tid] : 0;
    s[tid] = v;
    __syncthreads();
#pragma unroll
    for (int d = 1; d < 512; d <<= 1) {
        int t = (tid >= d) ? s[tid - d] : 0;
        __syncthreads();
        s[tid] += t;
        __syncthreads();
    }
    if (tid < nb) bsum[tid] = s[tid] - v;
}
__global__ void scan3(int* __restrict__ off, const int* __restrict__ bsum,
                      int* __restrict__ cur, int n, int E) {
    int i = blockIdx.x * 256 + threadIdx.x;
    if (i < n) {
        int o = off[i] + bsum[blockIdx.x];
        off[i] = o;
        cur[i] = o;
    }
    if (i == 0) off[n] = E;
}
__global__ void fill_csr(const int* __restrict__ row, const int* __restrict__ col,
                         int* __restrict__ cur, int* __restrict__ esrc,
                         int* __restrict__ eidx, int E) {
    int e = blockIdx.x * blockDim.x + threadIdx.x;
    if (e < E) {
        int p = atomicAdd(&cur[col[e]], 1);
        esrc[p] = row[e];
        eidx[p] = e;
    }
}

// ---------------- weight conversion ----------------
__global__ void conv_w(const float* __restrict__ src, __half* __restrict__ dst, int count) {
    int i = blockIdx.x * blockDim.x + threadIdx.x;
    if (i < count) dst[i] = __float2half_rn(src[i]);
}
__global__ void repack_wab_h(const float* __restrict__ l1W, __half* __restrict__ wabh) {
    int i = blockIdx.x * blockDim.x + threadIdx.x;
    if (i < 64 * 128) {
        int k = i >> 7, nn = i & 127;
        float v = (nn < 64) ? l1W[k * 64 + nn] : l1W[(64 + k) * 64 + (nn - 64)];
        wabh[i] = __float2half_rn(v);
    }
}

// ---------------- HMMA GEMM ----------------
template <int K, int N, bool SCALE, bool HALF_IN>
__global__ void gemm_mma(const void* __restrict__ Xv, const __half* __restrict__ Wh,
                         const float* __restrict__ dinv, __half2* __restrict__ Y, int nrows) {
    constexpr int XP = K + 8;
    constexpr int WP = N + 8;
    __shared__ __half Xs[64 * XP];
    __shared__ __half Ws[K * WP];
    int tid = threadIdx.x;
    int warp = tid >> 5, lane = tid & 31;
    int row0 = blockIdx.x * 64;

    if (HALF_IN) {
        const __half* X = (const __half*)Xv;
        for (int j = tid; j < 64 * (K / 8); j += 128) {
            int r = j / (K / 8), kq = j % (K / 8);
            int gr = row0 + r;
            uint4 u = make_uint4(0, 0, 0, 0);
            if (gr < nrows) u = *reinterpret_cast<const uint4*>(&X[(size_t)gr * K + kq * 8]);
            *reinterpret_cast<uint4*>(&Xs[r * XP + kq * 8]) = u;
        }
    } else {
        const float* X = (const float*)Xv;
        for (int j = tid; j < 64 * (K / 4); j += 128) {
            int r = j / (K / 4), kq = j % (K / 4);
            int gr = row0 + r;
            float4 v = (gr < nrows)
                ? *reinterpret_cast<const float4*>(&X[(size_t)gr * K + kq * 4])
                : make_float4(0.f, 0.f, 0.f, 0.f);
            __half2 h0 = __floats2half2_rn(v.x, v.y);
            __half2 h1 = __floats2half2_rn(v.z, v.w);
            uint2 u;
            u.x = *reinterpret_cast<unsigned*>(&h0);
            u.y = *reinterpret_cast<unsigned*>(&h1);
            *reinterpret_cast<uint2*>(&Xs[r * XP + kq * 4]) = u;
        }
    }
    for (int j = tid; j < K * (N / 8); j += 128) {
        int k = j / (N / 8), nq = j % (N / 8);
        *reinterpret_cast<uint4*>(&Ws[k * WP + nq * 8]) =
            *reinterpret_cast<const uint4*>(&Wh[(size_t)k * N + nq * 8]);
    }
    __syncthreads();

    float acc[N / 8][4];
#pragma unroll
    for (int nt = 0; nt < N / 8; nt++)
#pragma unroll
        for (int q = 0; q < 4; q++) acc[nt][q] = 0.f;

    int arow = warp * 16 + (lane & 15);
    int acol = (lane >> 4) * 8;
    int brow_l = lane & 15;

#pragma unroll
    for (int kt = 0; kt < K / 16; kt++) {
        unsigned a0, a1, a2, a3;
        unsigned aaddr = (unsigned)__cvta_generic_to_shared(&Xs[arow * XP + kt * 16 + acol]);
        asm volatile("ldmatrix.sync.aligned.m8n8.x4.shared.b16 {%0,%1,%2,%3}, [%4];"
                     : "=r"(a0), "=r"(a1), "=r"(a2), "=r"(a3) : "r"(aaddr));
#pragma unroll
        for (int nt = 0; nt < N / 8; nt++) {
            unsigned b0, b1;
            unsigned baddr = (unsigned)__cvta_generic_to_shared(
                &Ws[(kt * 16 + brow_l) * WP + nt * 8]);
            asm volatile("ldmatrix.sync.aligned.m8n8.x2.trans.shared.b16 {%0,%1}, [%2];"
                         : "=r"(b0), "=r"(b1) : "r"(baddr));
            asm volatile(
                "mma.sync.aligned.m16n8k16.row.col.f32.f16.f16.f32 "
                "{%0,%1,%2,%3}, {%4,%5,%6,%7}, {%8,%9}, {%0,%1,%2,%3};"
                : "+f"(acc[nt][0]), "+f"(acc[nt][1]), "+f"(acc[nt][2]), "+f"(acc[nt][3])
                : "r"(a0), "r"(a1), "r"(a2), "r"(a3), "r"(b0), "r"(b1));
        }
    }

    int rr = warp * 16 + (lane >> 2);
    int cq = lane & 3;
#pragma unroll
    for (int hh = 0; hh < 2; hh++) {
        int gr = row0 + rr + hh * 8;
        if (gr < nrows) {
            float s = SCALE ? dinv[gr] : 1.0f;
#pragma unroll
            for (int nt = 0; nt < N / 8; nt++) {
                __half2 p = __floats2half2_rn(acc[nt][hh * 2 + 0] * s,
                                              acc[nt][hh * 2 + 1] * s);
                Y[(size_t)gr * (N / 2) + nt * 4 + cq] = p;
            }
        }
    }
}

__device__ __forceinline__ __half2 as_h2(unsigned u) { return *reinterpret_cast<__half2*>(&u); }

__device__ __forceinline__ void acc_f32_u4(float4& a, float4& b, uint4 u) {
    float2 f0 = __half22float2(as_h2(u.x));
    float2 f1 = __half22float2(as_h2(u.y));
    float2 f2 = __half22float2(as_h2(u.z));
    float2 f3 = __half22float2(as_h2(u.w));
    a.x += f0.x; a.y += f0.y; a.z += f1.x; a.w += f1.y;
    b.x += f2.x; b.y += f2.y; b.z += f3.x; b.w += f3.y;
}
__device__ __forceinline__ void acc_w_u4(float4& a, float4& b, uint4 u, float w) {
    float2 f0 = __half22float2(as_h2(u.x));
    float2 f1 = __half22float2(as_h2(u.y));
    float2 f2 = __half22float2(as_h2(u.z));
    float2 f3 = __half22float2(as_h2(u.w));
    a.x += f0.x * w; a.y += f0.y * w; a.z += f1.x * w; a.w += f1.y * w;
    b.x += f2.x * w; b.y += f2.y * w; b.z += f3.x * w; b.w += f3.y * w;
}
__device__ __forceinline__ void acc_pair_u4(float4& a, float4& b, uint4 u0, uint4 u1) {
    __half2 p0 = __hadd2(as_h2(u0.x), as_h2(u1.x));
    __half2 p1 = __hadd2(as_h2(u0.y), as_h2(u1.y));
    __half2 p2 = __hadd2(as_h2(u0.z), as_h2(u1.z));
    __half2 p3 = __hadd2(as_h2(u0.w), as_h2(u1.w));
    float2 f0 = __half22float2(p0);
    float2 f1 = __half22float2(p1);
    float2 f2 = __half22float2(p2);
    float2 f3 = __half22float2(p3);
    a.x += f0.x; a.y += f0.y; a.z += f1.x; a.w += f1.y;
    b.x += f2.x; b.y += f2.y; b.z += f3.x; b.w += f3.y;
}

// ---------------- aggregation: 8 lanes/node; MLP=8 ----------------
// SCALE_SRC=true: hls unscaled -> weight each source by dinv[src]
// SCALE_SRC=false: hls pre-scaled -> pairwise fp16 adds
template <bool SCALE_SRC>
__global__ void gather_agg(const int* __restrict__ off, const int* __restrict__ esrc,
                           const __half2* __restrict__ hls, const float* __restrict__ dinv,
                           const float* __restrict__ bias, __half2* __restrict__ h, int n) {
    __shared__ float sb[64];
    if (threadIdx.x < 64) sb[threadIdx.x] = bias[threadIdx.x];
    __syncthreads();
    int gid = blockIdx.x * 256 + threadIdx.x;
    int c = gid >> 3;
    if (c >= n) return;
    int l = gid & 7;
    const uint4* hp = reinterpret_cast<const uint4*>(hls);
    float dc = dinv[c];
    float4 a = make_float4(0.f, 0.f, 0.f, 0.f);
    float4 b = make_float4(0.f, 0.f, 0.f, 0.f);
    if (SCALE_SRC) acc_w_u4(a, b, hp[(size_t)c * 8 + l], dc);
    else           acc_f32_u4(a, b, hp[(size_t)c * 8 + l]);
    int s = off[c], e2 = off[c + 1];
    int j = s;
    for (; j + 7 < e2; j += 8) {
        int r0 = esrc[j],     r1 = esrc[j + 1], r2 = esrc[j + 2], r3 = esrc[j + 3];
        int r4 = esrc[j + 4], r5 = esrc[j + 5], r6 = esrc[j + 6], r7 = esrc[j + 7];
        uint4 u0 = hp[(size_t)r0 * 8 + l];
        uint4 u1 = hp[(size_t)r1 * 8 + l];
        uint4 u2 = hp[(size_t)r2 * 8 + l];
        uint4 u3 = hp[(size_t)r3 * 8 + l];
        uint4 u4 = hp[(size_t)r4 * 8 + l];
        uint4 u5 = hp[(size_t)r5 * 8 + l];
        uint4 u6 = hp[(size_t)r6 * 8 + l];
        uint4 u7 = hp[(size_t)r7 * 8 + l];
        if (SCALE_SRC) {
            acc_w_u4(a, b, u0, dinv[r0]); acc_w_u4(a, b, u1, dinv[r1]);
            acc_w_u4(a, b, u2, dinv[r2]); acc_w_u4(a, b, u3, dinv[r3]);
            acc_w_u4(a, b, u4, dinv[r4]); acc_w_u4(a, b, u5, dinv[r5]);
            acc_w_u4(a, b, u6, dinv[r6]); acc_w_u4(a, b, u7, dinv[r7]);
        } else {
            acc_pair_u4(a, b, u0, u1);
            acc_pair_u4(a, b, u2, u3);
            acc_pair_u4(a, b, u4, u5);
            acc_pair_u4(a, b, u6, u7);
        }
    }
    for (; j + 1 < e2; j += 2) {
        int r0 = esrc[j], r1 = esrc[j + 1];
        uint4 u0 = hp[(size_t)r0 * 8 + l];
        uint4 u1 = hp[(size_t)r1 * 8 + l];
        if (SCALE_SRC) {
            acc_w_u4(a, b, u0, dinv[r0]);
            acc_w_u4(a, b, u1, dinv[r1]);
        } else {
            acc_pair_u4(a, b, u0, u1);
        }
    }
    if (j < e2) {
        int r = esrc[j];
        if (SCALE_SRC) acc_w_u4(a, b, hp[(size_t)r * 8 + l], dinv[r]);
        else           acc_f32_u4(a, b, hp[(size_t)r * 8 + l]);
    }
    int jb = l * 8;
    __half2 p0 = __floats2half2_rn(fmaxf(a.x * dc + sb[jb + 0], 0.f), fmaxf(a.y * dc + sb[jb + 1], 0.f));
    __half2 p1 = __floats2half2_rn(fmaxf(a.z * dc + sb[jb + 2], 0.f), fmaxf(a.w * dc + sb[jb + 3], 0.f));
    __half2 p2 = __floats2half2_rn(fmaxf(b.x * dc + sb[jb + 4], 0.f), fmaxf(b.y * dc + sb[jb + 5], 0.f));
    __half2 p3 = __floats2half2_rn(fmaxf(b.z * dc + sb[jb + 6], 0.f), fmaxf(b.w * dc + sb[jb + 7], 0.f));
    uint4 o;
    o.x = *reinterpret_cast<unsigned*>(&p0);
    o.y = *reinterpret_cast<unsigned*>(&p1);
    o.z = *reinterpret_cast<unsigned*>(&p2);
    o.w = *reinterpret_cast<unsigned*>(&p3);
    reinterpret_cast<uint4*>(h)[(size_t)c * 8 + l] = o;
}

// ---------------- edge MLP, CSC-ordered: 2 edges in flight ----------------
__device__ __forceinline__ float edge_dot(uint4 ua, __half2 hb0, __half2 hb1,
                                          __half2 hb2, __half2 hb3,
                                          float w0, float w1, float w2, float w3,
                                          float w4, float w5, float w6, float w7) {
    const __half2 hz = __float2half2_rn(0.f);
    __half2 z0 = __hmax2(__hadd2(as_h2(ua.x), hb0), hz);
    __half2 z1 = __hmax2(__hadd2(as_h2(ua.y), hb1), hz);
    __half2 z2 = __hmax2(__hadd2(as_h2(ua.z), hb2), hz);
    __half2 z3 = __hmax2(__hadd2(as_h2(ua.w), hb3), hz);
    float2 f0 = __half22float2(z0), f1 = __half22float2(z1);
    float2 f2 = __half22float2(z2), f3 = __half22float2(z3);
    return f0.x * w0 + f0.y * w1 + f1.x * w2 + f1.y * w3
         + f2.x * w4 + f2.y * w5 + f3.x * w6 + f3.y * w7;
}

__device__ __forceinline__ void emit_lsm(float d, float sdb, int e, float* __restrict__ out) {
    d += sdb;
    float lp = log1pf(__expf(-fabsf(d)));
    float o0 = (d > 0.f) ? -lp : (d - lp);
    *reinterpret_cast<float2*>(&out[2 * (size_t)e]) = make_float2(o0, o0 - d);
}

__global__ void edge_mlp_csc(const int* __restrict__ off, const int* __restrict__ esrc,
                             const int* __restrict__ eidx, const __half2* __restrict__ ab,
                             const float* __restrict__ l1b, const float* __restrict__ l2w,
                             const float* __restrict__ l2b, float* __restrict__ out, int n) {
    __shared__ __half2 s1bh[32];
    __shared__ float swd[64];
    __shared__ float sdb_s;
    int tid = threadIdx.x;
    if (tid < 32)       s1bh[tid] = __floats2half2_rn(l1b[tid * 2], l1b[tid * 2 + 1]);
    else if (tid < 96)  swd[tid - 32] = l2w[(tid - 32) * 2] - l2w[(tid - 32) * 2 + 1];
    else if (tid == 96) sdb_s = l2b[0] - l2b[1];
    __syncthreads();
    int gid = blockIdx.x * 256 + tid;
    int c = gid >> 3;
    if (c >= n) return;
    int l = gid & 7;
    float sdb = sdb_s;
    const uint4* ap = reinterpret_cast<const uint4*>(ab);
    uint4 ub = ap[(size_t)c * 16 + 8 + l];
    __half2 hb0 = __hadd2(as_h2(ub.x), s1bh[l * 4 + 0]);
    __half2 hb1 = __hadd2(as_h2(ub.y), s1bh[l * 4 + 1]);
    __half2 hb2 = __hadd2(as_h2(ub.z), s1bh[l * 4 + 2]);
    __half2 hb3 = __hadd2(as_h2(ub.w), s1bh[l * 4 + 3]);
    int j = l * 8;
    float w0 = swd[j + 0], w1 = swd[j + 1], w2 = swd[j + 2], w3 = swd[j + 3];
    float w4 = swd[j + 4], w5 = swd[j + 5], w6 = swd[j + 6], w7 = swd[j + 7];
    int s = off[c], e2 = off[c + 1];
    int p = s;
    for (; p + 1 < e2; p += 2) {
        uint4 ua0 = ap[(size_t)esrc[p]     * 16 + l];
        uint4 ua1 = ap[(size_t)esrc[p + 1] * 16 + l];
        float d0 = edge_dot(ua0, hb0, hb1, hb2, hb3, w0, w1, w2, w3, w4, w5, w6, w7);
        float d1 = edge_dot(ua1, hb0, hb1, hb2, hb3, w0, w1, w2, w3, w4, w5, w6, w7);
#pragma unroll
        for (int o = 4; o > 0; o >>= 1) {
            d0 += __shfl_down_sync(0xFFFFFFFFu, d0, o, 8);
            d1 += __shfl_down_sync(0xFFFFFFFFu, d1, o, 8);
        }
        if (l == 0) {
            emit_lsm(d0, sdb, eidx[p],     out);
            emit_lsm(d1, sdb, eidx[p + 1], out);
        }
    }
    if (p < e2) {
        uint4 ua = ap[(size_t)esrc[p] * 16 + l];
        float d = edge_dot(ua, hb0, hb1, hb2, hb3, w0, w1, w2, w3, w4, w5, w6, w7);
#pragma unroll
        for (int o = 4; o > 0; o >>= 1)
            d += __shfl_down_sync(0xFFFFFFFFu, d, o, 8);
        if (l == 0) emit_lsm(d, sdb, eidx[p], out);
    }
}

extern "C" void kernel_launch(void* const* d_in, const int* in_sizes, int n_in,
                              void* d_out, int out_size) {
    const float* x   = (const float*)d_in[0];
    const int*   ei  = (const int*)d_in[1];
    const float* W1  = (const float*)d_in[2];
    const float* b1  = (const float*)d_in[3];
    const float* W2  = (const float*)d_in[4];
    const float* b2  = (const float*)d_in[5];
    const float* l1W = (const float*)d_in[6];
    const float* l1b = (const float*)d_in[7];
    const float* l2W = (const float*)d_in[8];
    const float* l2b = (const float*)d_in[9];
    float* out = (float*)d_out;

    int n = in_sizes[0] / FIN;
    int E = in_sizes[1] / 2;
    const int* row = ei;
    const int* col = ei + E;

    int *cnt, *off, *cur, *esrc, *eidx, *bsum;
    float *dinv;
    __half2 *hl2, *h2, *ab2;
    __half *w1h, *w2h, *wabh;
    cudaGetSymbolAddress((void**)&cnt,  g_cnt);
    cudaGetSymbolAddress((void**)&off,  g_off);
    cudaGetSymbolAddress((void**)&cur,  g_cur);
    cudaGetSymbolAddress((void**)&esrc, g_esrc);
    cudaGetSymbolAddress((void**)&eidx, g_eidx);
    cudaGetSymbolAddress((void**)&bsum, g_bsum);
    cudaGetSymbolAddress((void**)&dinv, g_dinv);
    cudaGetSymbolAddress((void**)&hl2,  g_hl2);
    cudaGetSymbolAddress((void**)&h2,   g_h2);
    cudaGetSymbolAddress((void**)&ab2,  g_ab2);
    cudaGetSymbolAddress((void**)&w1h,  g_w1h);
    cudaGetSymbolAddress((void**)&w2h,  g_w2h);
    cudaGetSymbolAddress((void**)&wabh, g_wabh);

    const int T = 256;
    int NB = (n + 255) / 256;

    // fork: CSR build + weight conversions on side stream (independent of gemm1)
    cudaMemsetAsync(cnt, 0, (size_t)n * sizeof(int), 0);
    cudaEventRecord(g_evFork, 0);
    cudaStreamWaitEvent(g_s2, g_evFork, 0);
    count_in<<<(E + T - 1) / T, T, 0, g_s2>>>(col, cnt, E);
    scan1<<<NB, T, 0, g_s2>>>(cnt, off, bsum, dinv, n);
    scan2<<<1, 512, 0, g_s2>>>(bsum, NB);
    scan3<<<NB, T, 0, g_s2>>>(off, bsum, cur, n, E);
    fill_csr<<<(E + T - 1) / T, T, 0, g_s2>>>(row, col, cur, esrc, eidx, E);
    conv_w<<<(HIDD * HIDD + T - 1) / T, T, 0, g_s2>>>(W2, w2h, HIDD * HIDD);
    repack_wab_h<<<(64 * 128 + T - 1) / T, T, 0, g_s2>>>(l1W, wabh);
    cudaEventRecord(g_evJoin, g_s2);

    // main: conv W1 + gemm1 (UNscaled) run fully parallel with the CSR chain
    conv_w<<<(FIN * HIDD + T - 1) / T, T>>>(W1, w1h, FIN * HIDD);
    gemm_mma<128, 64, false, false><<<(n + 63) / 64, 128>>>(x, w1h, nullptr, hl2, n);
    cudaStreamWaitEvent(0, g_evJoin, 0);

    // layer 1: per-edge dinv scaling in gather
    gather_agg<true><<<(n * 8 + T - 1) / T, T>>>(off, esrc, hl2, dinv, b1, h2, n);

    // layer 2: pre-scaled in gemm2 epilogue, pairwise adds in gather
    gemm_mma<64, 64, true, true><<<(n + 63) / 64, 128>>>(h2, w2h, dinv, hl2, n);
    gather_agg<false><<<(n * 8 + T - 1) / T, T>>>(off, esrc, hl2, dinv, b2, h2, n);

    gemm_mma<64, 128, false, true><<<(n + 63) / 64, 128>>>(h2, wabh, nullptr, ab2, n);
    edge_mlp_csc<<<(n * 8 + T - 1) / T, T>>>(off, esrc, eidx, ab2, l1b, l2W, l2b, out, n);
}

// round 17
// speedup vs baseline: 1.0507x; 1.0507x over previous
#include <cuda_runtime.h>
#include <cuda_fp16.h>

#define NMAX 100000
#define EMAX 1600000
#define HIDD 64
#define FIN  128

__device__ int     g_cnt[NMAX];
__device__ int     g_off[NMAX + 1];
__device__ int     g_cur[NMAX];
__device__ int     g_esrc[EMAX];
__device__ int     g_eidx[EMAX];
__device__ int     g_bsum[512];
__device__ float   g_dinv[NMAX];
__device__ __half2 g_hl2[NMAX * HIDD / 2];   // fp16, PRE-SCALED by dinv[src]
__device__ __half2 g_h2 [NMAX * HIDD / 2];   // fp16 aggregated features
__device__ __half2 g_ab2[NMAX * HIDD];       // fp16 [A|B] table
__device__ __half  g_w1h[FIN * HIDD];
__device__ __half  g_w2h[HIDD * HIDD];
__device__ __half  g_wabh[HIDD * 2 * HIDD];

static cudaStream_t g_s2;
static cudaEvent_t g_evFork, g_evDinv, g_evJoin;
namespace { struct StreamInit {
    StreamInit() {
        cudaStreamCreateWithFlags(&g_s2, cudaStreamNonBlocking);
        cudaEventCreateWithFlags(&g_evFork, cudaEventDisableTiming);
        cudaEventCreateWithFlags(&g_evDinv, cudaEventDisableTiming);
        cudaEventCreateWithFlags(&g_evJoin, cudaEventDisableTiming);
    }
} g_streamInit; }

// ---------------- CSC build ----------------
__global__ void count_in(const int* __restrict__ col, int* __restrict__ cnt, int E) {
    int e = blockIdx.x * blockDim.x + threadIdx.x;
    if (e < E) atomicAdd(&cnt[col[e]], 1);
}
__global__ void scan1(const int* __restrict__ cnt, int* __restrict__ off,
                      int* __restrict__ bsum, float* __restrict__ dinv, int n) {
    __shared__ int s[256];
    int tid = threadIdx.x;
    int i = blockIdx.x * 256 + tid;
    int v = (i < n) ? cnt[i] : 0;
    if (i < n) dinv[i] = rsqrtf((float)v + 1.0f);
    s[tid] = v;
    __syncthreads();
#pragma unroll
    for (int d = 1; d < 256; d <<= 1) {
        int t = (tid >= d) ? s[tid - d] : 0;
        __syncthreads();
        s[tid] += t;
        __syncthreads();
    }
    if (i < n) off[i] = s[tid] - v;
    if (tid == 255) bsum[blockIdx.x] = s[255];
}
__global__ void scan2(int* __restrict__ bsum, int nb) {
    __shared__ int s[512];
    int tid = threadIdx.x;
    int v = (tid < nb) ? bsum[tid] : 0;
    s[tid] = v;
    __syncthreads();
#pragma unroll
    for (int d = 1; d < 512; d <<= 1) {
        int t = (tid >= d) ? s[tid - d] : 0;
        __syncthreads();
        s[tid] += t;
        __syncthreads();
    }
    if (tid < nb) bsum[tid] = s[tid] - v;
}
__global__ void scan3(int* __restrict__ off, const int* __restrict__ bsum,
                      int* __restrict__ cur, int n, int E) {
    int i = blockIdx.x * 256 + threadIdx.x;
    if (i < n) {
        int o = off[i] + bsum[blockIdx.x];
        off[i] = o;
        cur[i] = o;
    }
    if (i == 0) off[n] = E;
}
__global__ void fill_csr(const int* __restrict__ row, const int* __restrict__ col,
                         int* __restrict__ cur, int* __restrict__ esrc,
                         int* __restrict__ eidx, int E) {
    int e = blockIdx.x * blockDim.x + threadIdx.x;
    if (e < E) {
        int p = atomicAdd(&cur[col[e]], 1);
        esrc[p] = row[e];
        eidx[p] = e;
    }
}

// ---------------- weight conversion ----------------
__global__ void conv_w(const float* __restrict__ src, __half* __restrict__ dst, int count) {
    int i = blockIdx.x * blockDim.x + threadIdx.x;
    if (i < count) dst[i] = __float2half_rn(src[i]);
}
__global__ void repack_wab_h(const float* __restrict__ l1W, __half* __restrict__ wabh) {
    int i = blockIdx.x * blockDim.x + threadIdx.x;
    if (i < 64 * 128) {
        int k = i >> 7, nn = i & 127;
        float v = (nn < 64) ? l1W[k * 64 + nn] : l1W[(64 + k) * 64 + (nn - 64)];
        wabh[i] = __float2half_rn(v);
    }
}

// ---------------- HMMA GEMM ----------------
template <int K, int N, bool SCALE, bool HALF_IN>
__global__ void gemm_mma(const void* __restrict__ Xv, const __half* __restrict__ Wh,
                         const float* __restrict__ dinv, __half2* __restrict__ Y, int nrows) {
    constexpr int XP = K + 8;
    constexpr int WP = N + 8;
    __shared__ __half Xs[64 * XP];
    __shared__ __half Ws[K * WP];
    int tid = threadIdx.x;
    int warp = tid >> 5, lane = tid & 31;
    int row0 = blockIdx.x * 64;

    if (HALF_IN) {
        const __half* X = (const __half*)Xv;
        for (int j = tid; j < 64 * (K / 8); j += 128) {
            int r = j / (K / 8), kq = j % (K / 8);
            int gr = row0 + r;
            uint4 u = make_uint4(0, 0, 0, 0);
            if (gr < nrows) u = *reinterpret_cast<const uint4*>(&X[(size_t)gr * K + kq * 8]);
            *reinterpret_cast<uint4*>(&Xs[r * XP + kq * 8]) = u;
        }
    } else {
        const float* X = (const float*)Xv;
        for (int j = tid; j < 64 * (K / 4); j += 128) {
            int r = j / (K / 4), kq = j % (K / 4);
            int gr = row0 + r;
            float4 v = (gr < nrows)
                ? *reinterpret_cast<const float4*>(&X[(size_t)gr * K + kq * 4])
                : make_float4(0.f, 0.f, 0.f, 0.f);
            __half2 h0 = __floats2half2_rn(v.x, v.y);
            __half2 h1 = __floats2half2_rn(v.z, v.w);
            uint2 u;
            u.x = *reinterpret_cast<unsigned*>(&h0);
            u.y = *reinterpret_cast<unsigned*>(&h1);
            *reinterpret_cast<uint2*>(&Xs[r * XP + kq * 4]) = u;
        }
    }
    for (int j = tid; j < K * (N / 8); j += 128) {
        int k = j / (N / 8), nq = j % (N / 8);
        *reinterpret_cast<uint4*>(&Ws[k * WP + nq * 8]) =
            *reinterpret_cast<const uint4*>(&Wh[(size_t)k * N + nq * 8]);
    }
    __syncthreads();

    float acc[N / 8][4];
#pragma unroll
    for (int nt = 0; nt < N / 8; nt++)
#pragma unroll
        for (int q = 0; q < 4; q++) acc[nt][q] = 0.f;

    int arow = warp * 16 + (lane & 15);
    int acol = (lane >> 4) * 8;
    int brow_l = lane & 15;

#pragma unroll
    for (int kt = 0; kt < K / 16; kt++) {
        unsigned a0, a1, a2, a3;
        unsigned aaddr = (unsigned)__cvta_generic_to_shared(&Xs[arow * XP + kt * 16 + acol]);
        asm volatile("ldmatrix.sync.aligned.m8n8.x4.shared.b16 {%0,%1,%2,%3}, [%4];"
                     : "=r"(a0), "=r"(a1), "=r"(a2), "=r"(a3) : "r"(aaddr));
#pragma unroll
        for (int nt = 0; nt < N / 8; nt++) {
            unsigned b0, b1;
            unsigned baddr = (unsigned)__cvta_generic_to_shared(
                &Ws[(kt * 16 + brow_l) * WP + nt * 8]);
            asm volatile("ldmatrix.sync.aligned.m8n8.x2.trans.shared.b16 {%0,%1}, [%2];"
                         : "=r"(b0), "=r"(b1) : "r"(baddr));
            asm volatile(
                "mma.sync.aligned.m16n8k16.row.col.f32.f16.f16.f32 "
                "{%0,%1,%2,%3}, {%4,%5,%6,%7}, {%8,%9}, {%0,%1,%2,%3};"
                : "+f"(acc[nt][0]), "+f"(acc[nt][1]), "+f"(acc[nt][2]), "+f"(acc[nt][3])
                : "r"(a0), "r"(a1), "r"(a2), "r"(a3), "r"(b0), "r"(b1));
        }
    }

    int rr = warp * 16 + (lane >> 2);
    int cq = lane & 3;
#pragma unroll
    for (int hh = 0; hh < 2; hh++) {
        int gr = row0 + rr + hh * 8;
        if (gr < nrows) {
            float s = SCALE ? dinv[gr] : 1.0f;
#pragma unroll
            for (int nt = 0; nt < N / 8; nt++) {
                __half2 p = __floats2half2_rn(acc[nt][hh * 2 + 0] * s,
                                              acc[nt][hh * 2 + 1] * s);
                Y[(size_t)gr * (N / 2) + nt * 4 + cq] = p;
            }
        }
    }
}

__device__ __forceinline__ __half2 as_h2(unsigned u) { return *reinterpret_cast<__half2*>(&u); }

__device__ __forceinline__ void acc_f32_u4(float4& a, float4& b, uint4 u) {
    float2 f0 = __half22float2(as_h2(u.x));
    float2 f1 = __half22float2(as_h2(u.y));
    float2 f2 = __half22float2(as_h2(u.z));
    float2 f3 = __half22float2(as_h2(u.w));
    a.x += f0.x; a.y += f0.y; a.z += f1.x; a.w += f1.y;
    b.x += f2.x; b.y += f2.y; b.z += f3.x; b.w += f3.y;
}
__device__ __forceinline__ void acc_pair_u4(float4& a, float4& b, uint4 u0, uint4 u1) {
    __half2 p0 = __hadd2(as_h2(u0.x), as_h2(u1.x));
    __half2 p1 = __hadd2(as_h2(u0.y), as_h2(u1.y));
    __half2 p2 = __hadd2(as_h2(u0.z), as_h2(u1.z));
    __half2 p3 = __hadd2(as_h2(u0.w), as_h2(u1.w));
    float2 f0 = __half22float2(p0);
    float2 f1 = __half22float2(p1);
    float2 f2 = __half22float2(p2);
    float2 f3 = __half22float2(p3);
    a.x += f0.x; a.y += f0.y; a.z += f1.x; a.w += f1.y;
    b.x += f2.x; b.y += f2.y; b.z += f3.x; b.w += f3.y;
}

// ---------------- aggregation: sources pre-scaled; 8 lanes/node; MLP=8 ----------------
__global__ void gather_agg(const int* __restrict__ off, const int* __restrict__ esrc,
                           const __half2* __restrict__ hls, const float* __restrict__ dinv,
                           const float* __restrict__ bias, __half2* __restrict__ h, int n) {
    __shared__ float sb[64];
    if (threadIdx.x < 64) sb[threadIdx.x] = bias[threadIdx.x];
    __syncthreads();
    int gid = blockIdx.x * 256 + threadIdx.x;
    int c = gid >> 3;
    if (c >= n) return;
    int l = gid & 7;
    const uint4* hp = reinterpret_cast<const uint4*>(hls);
    float dc = dinv[c];
    float4 a = make_float4(0.f, 0.f, 0.f, 0.f);
    float4 b = make_float4(0.f, 0.f, 0.f, 0.f);
    acc_f32_u4(a, b, hp[(size_t)c * 8 + l]);  // self (pre-scaled)
    int s = off[c], e2 = off[c + 1];
    int j = s;
    for (; j + 7 < e2; j += 8) {
        int r0 = esrc[j],     r1 = esrc[j + 1], r2 = esrc[j + 2], r3 = esrc[j + 3];
        int r4 = esrc[j + 4], r5 = esrc[j + 5], r6 = esrc[j + 6], r7 = esrc[j + 7];
        uint4 u0 = hp[(size_t)r0 * 8 + l];
        uint4 u1 = hp[(size_t)r1 * 8 + l];
        uint4 u2 = hp[(size_t)r2 * 8 + l];
        uint4 u3 = hp[(size_t)r3 * 8 + l];
        uint4 u4 = hp[(size_t)r4 * 8 + l];
        uint4 u5 = hp[(size_t)r5 * 8 + l];
        uint4 u6 = hp[(size_t)r6 * 8 + l];
        uint4 u7 = hp[(size_t)r7 * 8 + l];
        acc_pair_u4(a, b, u0, u1);
        acc_pair_u4(a, b, u2, u3);
        acc_pair_u4(a, b, u4, u5);
        acc_pair_u4(a, b, u6, u7);
    }
    for (; j + 1 < e2; j += 2) {
        uint4 u0 = hp[(size_t)esrc[j]     * 8 + l];
        uint4 u1 = hp[(size_t)esrc[j + 1] * 8 + l];
        acc_pair_u4(a, b, u0, u1);
    }
    if (j < e2) acc_f32_u4(a, b, hp[(size_t)esrc[j] * 8 + l]);
    int jb = l * 8;
    __half2 p0 = __floats2half2_rn(fmaxf(a.x * dc + sb[jb + 0], 0.f), fmaxf(a.y * dc + sb[jb + 1], 0.f));
    __half2 p1 = __floats2half2_rn(fmaxf(a.z * dc + sb[jb + 2], 0.f), fmaxf(a.w * dc + sb[jb + 3], 0.f));
    __half2 p2 = __floats2half2_rn(fmaxf(b.x * dc + sb[jb + 4], 0.f), fmaxf(b.y * dc + sb[jb + 5], 0.f));
    __half2 p3 = __floats2half2_rn(fmaxf(b.z * dc + sb[jb + 6], 0.f), fmaxf(b.w * dc + sb[jb + 7], 0.f));
    uint4 o;
    o.x = *reinterpret_cast<unsigned*>(&p0);
    o.y = *reinterpret_cast<unsigned*>(&p1);
    o.z = *reinterpret_cast<unsigned*>(&p2);
    o.w = *reinterpret_cast<unsigned*>(&p3);
    reinterpret_cast<uint4*>(h)[(size_t)c * 8 + l] = o;
}

// ---------------- edge MLP, CSC-ordered: 2 edges in flight ----------------
__device__ __forceinline__ float edge_dot(uint4 ua, __half2 hb0, __half2 hb1,
                                          __half2 hb2, __half2 hb3,
                                          float w0, float w1, float w2, float w3,
                                          float w4, float w5, float w6, float w7) {
    const __half2 hz = __float2half2_rn(0.f);
    __half2 z0 = __hmax2(__hadd2(as_h2(ua.x), hb0), hz);
    __half2 z1 = __hmax2(__hadd2(as_h2(ua.y), hb1), hz);
    __half2 z2 = __hmax2(__hadd2(as_h2(ua.z), hb2), hz);
    __half2 z3 = __hmax2(__hadd2(as_h2(ua.w), hb3), hz);
    float2 f0 = __half22float2(z0), f1 = __half22float2(z1);
    float2 f2 = __half22float2(z2), f3 = __half22float2(z3);
    return f0.x * w0 + f0.y * w1 + f1.x * w2 + f1.y * w3
         + f2.x * w4 + f2.y * w5 + f3.x * w6 + f3.y * w7;
}

__device__ __forceinline__ void emit_lsm(float d, float sdb, int e, float* __restrict__ out) {
    d += sdb;
    float lp = log1pf(__expf(-fabsf(d)));
    float o0 = (d > 0.f) ? -lp : (d - lp);
    *reinterpret_cast<float2*>(&out[2 * (size_t)e]) = make_float2(o0, o0 - d);
}

__global__ void edge_mlp_csc(const int* __restrict__ off, const int* __restrict__ esrc,
                             const int* __restrict__ eidx, const __half2* __restrict__ ab,
                             const float* __restrict__ l1b, const float* __restrict__ l2w,
                             const float* __restrict__ l2b, float* __restrict__ out, int n) {
    __shared__ __half2 s1bh[32];
    __shared__ float swd[64];
    __shared__ float sdb_s;
    int tid = threadIdx.x;
    if (tid < 32)       s1bh[tid] = __floats2half2_rn(l1b[tid * 2], l1b[tid * 2 + 1]);
    else if (tid < 96)  swd[tid - 32] = l2w[(tid - 32) * 2] - l2w[(tid - 32) * 2 + 1];
    else if (tid == 96) sdb_s = l2b[0] - l2b[1];
    __syncthreads();
    int gid = blockIdx.x * 256 + tid;
    int c = gid >> 3;
    if (c >= n) return;
    int l = gid & 7;
    float sdb = sdb_s;
    const uint4* ap = reinterpret_cast<const uint4*>(ab);
    uint4 ub = ap[(size_t)c * 16 + 8 + l];
    __half2 hb0 = __hadd2(as_h2(ub.x), s1bh[l * 4 + 0]);
    __half2 hb1 = __hadd2(as_h2(ub.y), s1bh[l * 4 + 1]);
    __half2 hb2 = __hadd2(as_h2(ub.z), s1bh[l * 4 + 2]);
    __half2 hb3 = __hadd2(as_h2(ub.w), s1bh[l * 4 + 3]);
    int j = l * 8;
    float w0 = swd[j + 0], w1 = swd[j + 1], w2 = swd[j + 2], w3 = swd[j + 3];
    float w4 = swd[j + 4], w5 = swd[j + 5], w6 = swd[j + 6], w7 = swd[j + 7];
    int s = off[c], e2 = off[c + 1];
    int p = s;
    for (; p + 1 < e2; p += 2) {
        uint4 ua0 = ap[(size_t)esrc[p]     * 16 + l];
        uint4 ua1 = ap[(size_t)esrc[p + 1] * 16 + l];
        float d0 = edge_dot(ua0, hb0, hb1, hb2, hb3, w0, w1, w2, w3, w4, w5, w6, w7);
        float d1 = edge_dot(ua1, hb0, hb1, hb2, hb3, w0, w1, w2, w3, w4, w5, w6, w7);
#pragma unroll
        for (int o = 4; o > 0; o >>= 1) {
            d0 += __shfl_down_sync(0xFFFFFFFFu, d0, o, 8);
            d1 += __shfl_down_sync(0xFFFFFFFFu, d1, o, 8);
        }
        if (l == 0) {
            emit_lsm(d0, sdb, eidx[p],     out);
            emit_lsm(d1, sdb, eidx[p + 1], out);
        }
    }
    if (p < e2) {
        uint4 ua = ap[(size_t)esrc[p] * 16 + l];
        float d = edge_dot(ua, hb0, hb1, hb2, hb3, w0, w1, w2, w3, w4, w5, w6, w7);
#pragma unroll
        for (int o = 4; o > 0; o >>= 1)
            d += __shfl_down_sync(0xFFFFFFFFu, d, o, 8);
        if (l == 0) emit_lsm(d, sdb, eidx[p], out);
    }
}

extern "C" void kernel_launch(void* const* d_in, const int* in_sizes, int n_in,
                              void* d_out, int out_size) {
    const float* x   = (const float*)d_in[0];
    const int*   ei  = (const int*)d_in[1];
    const float* W1  = (const float*)d_in[2];
    const float* b1  = (const float*)d_in[3];
    const float* W2  = (const float*)d_in[4];
    const float* b2  = (const float*)d_in[5];
    const float* l1W = (const float*)d_in[6];
    const float* l1b = (const float*)d_in[7];
    const float* l2W = (const float*)d_in[8];
    const float* l2b = (const float*)d_in[9];
    float* out = (float*)d_out;

    int n = in_sizes[0] / FIN;
    int E = in_sizes[1] / 2;
    const int* row = ei;
    const int* col = ei + E;

    int *cnt, *off, *cur, *esrc, *eidx, *bsum;
    float *dinv;
    __half2 *hl2, *h2, *ab2;
    __half *w1h, *w2h, *wabh;
    cudaGetSymbolAddress((void**)&cnt,  g_cnt);
    cudaGetSymbolAddress((void**)&off,  g_off);
    cudaGetSymbolAddress((void**)&cur,  g_cur);
    cudaGetSymbolAddress((void**)&esrc, g_esrc);
    cudaGetSymbolAddress((void**)&eidx, g_eidx);
    cudaGetSymbolAddress((void**)&bsum, g_bsum);
    cudaGetSymbolAddress((void**)&dinv, g_dinv);
    cudaGetSymbolAddress((void**)&hl2,  g_hl2);
    cudaGetSymbolAddress((void**)&h2,   g_h2);
    cudaGetSymbolAddress((void**)&ab2,  g_ab2);
    cudaGetSymbolAddress((void**)&w1h,  g_w1h);
    cudaGetSymbolAddress((void**)&w2h,  g_w2h);
    cudaGetSymbolAddress((void**)&wabh, g_wabh);

    const int T = 256;
    int NB = (n + 255) / 256;

    // fork: CSR build ONLY on side stream; evJoin right after fill_csr
    cudaMemsetAsync(cnt, 0, (size_t)n * sizeof(int), 0);
    cudaEventRecord(g_evFork, 0);
    cudaStreamWaitEvent(g_s2, g_evFork, 0);
    count_in<<<(E + T - 1) / T, T, 0, g_s2>>>(col, cnt, E);
    scan1<<<NB, T, 0, g_s2>>>(cnt, off, bsum, dinv, n);
    cudaEventRecord(g_evDinv, g_s2);          // dinv ready early
    scan2<<<1, 512, 0, g_s2>>>(bsum, NB);
    scan3<<<NB, T, 0, g_s2>>>(off, bsum, cur, n, E);
    fill_csr<<<(E + T - 1) / T, T, 0, g_s2>>>(row, col, cur, esrc, eidx, E);
    cudaEventRecord(g_evJoin, g_s2);

    // main: all weight prep fits in the evDinv wait window; gemm1 (scaled) after dinv
    conv_w<<<(FIN * HIDD + T - 1) / T, T>>>(W1, w1h, FIN * HIDD);
    conv_w<<<(HIDD * HIDD + T - 1) / T, T>>>(W2, w2h, HIDD * HIDD);
    repack_wab_h<<<(64 * 128 + T - 1) / T, T>>>(l1W, wabh);
    cudaStreamWaitEvent(0, g_evDinv, 0);
    gemm_mma<128, 64, true, false><<<(n + 63) / 64, 128>>>(x, w1h, dinv, hl2, n);
    cudaStreamWaitEvent(0, g_evJoin, 0);

    gather_agg<<<(n * 8 + T - 1) / T, T>>>(off, esrc, hl2, dinv, b1, h2, n);

    gemm_mma<64, 64, true, true><<<(n + 63) / 64, 128>>>(h2, w2h, dinv, hl2, n);
    gather_agg<<<(n * 8 + T - 1) / T, T>>>(off, esrc, hl2, dinv, b2, h2, n);

    gemm_mma<64, 128, false, true><<<(n + 63) / 64, 128>>>(h2, wabh, nullptr, ab2, n);
    edge_mlp_csc<<<(n * 8 + T - 1) / T, T>>>(off, esrc, eidx, ab2, l1b, l2W, l2b, out, n);
}